// round 11
// baseline (speedup 1.0000x reference)
#include <cuda_runtime.h>
#include <cstdint>

#define N_ENT 50000
#define R_REL 16
#define D_EMB 64
#define F_IN  128
#define E_EDGE 100000
#define NEDGE (R_REL * E_EDGE)          // 1.6M
#define NK (R_REL * N_ENT)              // 800000 keys (r*N + col)
#define NL 2

// ---------------- scratch (device globals; allocation-free rule) ------------
__device__ float g_emb[(size_t)N_ENT * D_EMB];                 // 12.8 MB
__device__ float g_acc1[(size_t)N_ENT * D_EMB];                // 12.8 MB (L2-hot)
__device__ float g_acc2[(size_t)N_ENT * D_EMB];                // 12.8 MB (L2-hot)
__device__ int   g_counts[NK];
__device__ int   g_rowstart[NK + 1];
__device__ int   g_cursor[NK];
__device__ int2  g_recs[NEDGE];          // {(dest_row<<7)|col_local, val bits}

#define SCHUNK 1024
#define NCH ((NK + SCHUNK - 1) / SCHUNK)                       // 782
__device__ int   g_part[NCH];

#define CVT_BF16X2(res, a, b) \
    asm("cvt.rn.satfinite.bf16x2.f32 %0, %1, %2;" : "=r"(res) : "f"(b), "f"(a))

__device__ __forceinline__ void split_pair(float2 f, uint32_t& h, uint32_t& l) {
    CVT_BF16X2(h, f.x, f.y);
    float h0 = __uint_as_float(h << 16);
    float h1 = __uint_as_float(h & 0xFFFF0000u);
    CVT_BF16X2(l, f.x - h0, f.y - h1);
}

// ---------------------------------------------------------------------------
// Input GEMM (proven): g_emb = x @ ent_emb  (K=128)
// ---------------------------------------------------------------------------
#define KS_IN 132

__global__ void k_input_gemm(const float* __restrict__ x,
                             const float* __restrict__ ent_emb,
                             int nrows) {
    extern __shared__ float smemf[];
    float* sA  = smemf;
    float* sBt = smemf + 64 * KS_IN;

    const int tid  = threadIdx.x;
    const int base = blockIdx.x * 64;

    for (int idx = tid; idx < F_IN * D_EMB; idx += 256) {
        int k = idx / D_EMB, d = idx % D_EMB;
        sBt[d * KS_IN + k] = ent_emb[idx];
    }
    for (int idx4 = tid; idx4 < 64 * (F_IN / 4); idx4 += 256) {
        int row = idx4 / (F_IN / 4), kq = idx4 % (F_IN / 4);
        float4 v = make_float4(0.f, 0.f, 0.f, 0.f);
        if (base + row < nrows)
            v = reinterpret_cast<const float4*>(x + (size_t)(base + row) * F_IN)[kq];
        *reinterpret_cast<float4*>(&sA[row * KS_IN + kq * 4]) = v;
    }
    __syncthreads();

    const int cs = tid & 15;
    const int rs = tid >> 4;
    float acc[4][4];
#pragma unroll
    for (int i = 0; i < 4; i++)
#pragma unroll
        for (int j = 0; j < 4; j++) acc[i][j] = 0.f;

#pragma unroll 8
    for (int kq = 0; kq < F_IN / 4; kq++) {
        float4 a[4], b[4];
#pragma unroll
        for (int i = 0; i < 4; i++)
            a[i] = *reinterpret_cast<const float4*>(&sA[(rs + 16 * i) * KS_IN + kq * 4]);
#pragma unroll
        for (int j = 0; j < 4; j++)
            b[j] = *reinterpret_cast<const float4*>(&sBt[(cs + 16 * j) * KS_IN + kq * 4]);
#pragma unroll
        for (int i = 0; i < 4; i++)
#pragma unroll
            for (int j = 0; j < 4; j++)
                acc[i][j] += a[i].x * b[j].x + a[i].y * b[j].y +
                             a[i].z * b[j].z + a[i].w * b[j].w;
    }

#pragma unroll
    for (int i = 0; i < 4; i++) {
        int row = base + rs + 16 * i;
        if (row < nrows) {
#pragma unroll
            for (int j = 0; j < 4; j++)
                g_emb[(size_t)row * D_EMB + cs + 16 * j] = acc[i][j];
        }
    }
}

// ---------------------------------------------------------------------------
// CSC build over keys = r*N_ENT + col  (proven)
// ---------------------------------------------------------------------------
__global__ void k_zero_counts() {
    int i = blockIdx.x * blockDim.x + threadIdx.x;
    if (i < NK / 4)
        reinterpret_cast<int4*>(g_counts)[i] = make_int4(0, 0, 0, 0);
}

__global__ void k_hist(const int* __restrict__ ecol) {
    int i = blockIdx.x * blockDim.x + threadIdx.x;
    if (i >= NEDGE) return;
    int r = i / E_EDGE;
    atomicAdd(&g_counts[r * N_ENT + __ldg(ecol + i)], 1);
}

__global__ void k_scan1() {
    __shared__ int ss[256];
    int b = blockIdx.x, t = threadIdx.x;
    int base = b * SCHUNK + t * 4;
    int4 c = make_int4(0, 0, 0, 0);
    if (base < NK) c = *reinterpret_cast<const int4*>(&g_counts[base]);
    int s = c.x + c.y + c.z + c.w;
    ss[t] = s;
    __syncthreads();
    for (int off = 1; off < 256; off <<= 1) {
        int v = (t >= off) ? ss[t - off] : 0;
        __syncthreads();
        ss[t] += v;
        __syncthreads();
    }
    int excl = ss[t] - s;
    if (t == 255) g_part[b] = ss[t];
    if (base < NK) {
        int r = excl;
        g_rowstart[base + 0] = r; r += c.x;
        g_rowstart[base + 1] = r; r += c.y;
        g_rowstart[base + 2] = r; r += c.z;
        g_rowstart[base + 3] = r;
    }
}

__global__ void k_scan2() {
    __shared__ int sp[1024];
    int t = threadIdx.x;
    int v = (t < NCH) ? g_part[t] : 0;
    sp[t] = v;
    __syncthreads();
    for (int off = 1; off < 1024; off <<= 1) {
        int x = (t >= off) ? sp[t - off] : 0;
        __syncthreads();
        sp[t] += x;
        __syncthreads();
    }
    if (t < NCH) g_part[t] = sp[t] - v;
    if (t == 1023) g_rowstart[NK] = sp[1023];
}

__global__ void k_scan3() {
    int i = blockIdx.x * blockDim.x + threadIdx.x;
    if (i < NK) {
        int v = g_rowstart[i] + g_part[i >> 10];
        g_rowstart[i] = v;
        g_cursor[i] = v;
    }
}

__global__ void k_place(const int* __restrict__ erow,
                        const int* __restrict__ ecol,
                        const float* __restrict__ eval) {
    int i = blockIdx.x * blockDim.x + threadIdx.x;
    if (i >= NEDGE) return;
    int r   = i / E_EDGE;
    int col = __ldg(ecol + i);
    int key = r * N_ENT + col;
    int pos = atomicAdd(&g_cursor[key], 1);
    g_recs[pos] = make_int2((__ldg(erow + i) << 7) | (col & 127),
                            __float_as_int(__ldg(eval + i)));
}

// ---------------------------------------------------------------------------
// Zero an acc buffer. sel: 0 -> g_acc1, 1 -> g_acc2
// ---------------------------------------------------------------------------
__global__ void k_zero_acc(int sel) {
    int i = blockIdx.x * blockDim.x + threadIdx.x;
    float* a = sel ? g_acc2 : g_acc1;
    if (i < N_ENT * D_EMB / 4)
        reinterpret_cast<float4*>(a)[i] = make_float4(0.f, 0.f, 0.f, 0.f);
}

// ---------------------------------------------------------------------------
// FUSED layer (round-10 proven math; tighter regions, single B buffer
// -> 89KB smem -> 2 CTAs/SM):
//   region1: scatter_{r-1} (REDG, fire-and-forget) + MMA_r (reads A,B)
//   sync
//   region2: write sY_r + stage B_{r+1}
//   sync
// src_sel: 0 -> A=g_emb, out=g_acc1 ; 1 -> A=relu(g_acc1), out=g_acc2
// ---------------------------------------------------------------------------
#define AW 36
#define BW 68
#define YW 68
#define SM_AH 0
#define SM_AL (128 * AW)                        // 4608
#define SM_B  (2 * 128 * AW)                    // 9216 (hi at +0, lo at +32*BW)
#define SM_Y  (SM_B + 2 * 32 * BW)              // 13568
#define SM_TOT (SM_Y + 128 * YW)                // 22272 words = 89088 B

#define MMA_BF16(c, a, b0, b1) \
    asm volatile("mma.sync.aligned.m16n8k16.row.col.f32.bf16.bf16.f32 " \
        "{%0,%1,%2,%3}, {%4,%5,%6,%7}, {%8,%9}, {%0,%1,%2,%3};" \
        : "+f"((c)[0]), "+f"((c)[1]), "+f"((c)[2]), "+f"((c)[3]) \
        : "r"((a)[0]), "r"((a)[1]), "r"((a)[2]), "r"((a)[3]), \
          "r"(b0), "r"(b1))

__global__ void __launch_bounds__(256)
k_layer_fused(const float* __restrict__ rel_trans, int layer,
              int src_sel, int nrows) {
    extern __shared__ uint32_t sw[];
    uint32_t* sAh = sw + SM_AH;
    uint32_t* sAl = sw + SM_AL;
    uint32_t* sBh = sw + SM_B;
    uint32_t* sBl = sBh + 32 * BW;
    float*    sY  = reinterpret_cast<float*>(sw + SM_Y);

    const int tid  = threadIdx.x;
    const int base = blockIdx.x * 128;
    const float* Wl   = rel_trans + (size_t)layer * R_REL * D_EMB * D_EMB;
    const float* Asrc = src_sel ? g_acc1 : g_emb;
    float*       aout = src_sel ? g_acc2 : g_acc1;

    // ---- stage A once ----
#pragma unroll
    for (int i = 0; i < 16; i++) {
        int p   = tid + i * 256;
        int row = p >> 5;
        int e2  = p & 31;
        float2 f = make_float2(0.f, 0.f);
        if (base + row < nrows)
            f = *reinterpret_cast<const float2*>(
                Asrc + (size_t)(base + row) * D_EMB + e2 * 2);
        if (src_sel) { f.x = fmaxf(f.x, 0.f); f.y = fmaxf(f.y, 0.f); }
        uint32_t h, l; split_pair(f, h, l);
        sAh[row * AW + e2] = h;
        sAl[row * AW + e2] = l;
    }

    // ---- stage B_0 ----
#pragma unroll
    for (int i = 0; i < 8; i++) {
        int p  = tid + i * 256;
        int d  = p >> 5;
        int e2 = p & 31;
        float2 f = *reinterpret_cast<const float2*>(Wl + d * 64 + e2 * 2);
        uint32_t h, l; split_pair(f, h, l);
        sBh[e2 * BW + d] = h;
        sBl[e2 * BW + d] = l;
    }
    __syncthreads();

    const int warp = tid >> 5;
    const int lane = tid & 31;
    const int g = lane >> 2;
    const int t = lane & 3;
    const int wrow = warp * 16;
    const int d4 = tid & 15;
    const int eoff = tid >> 4;
    const int tile_hi = (base + 128 < nrows) ? base + 128 : nrows;

    for (int r = 0; r < R_REL; r++) {
        // ---- region1: scatter_{r-1} + MMA_r ----
        if (r > 0) {
            int rp = r - 1;
            int j0 = __ldg(&g_rowstart[rp * N_ENT + base]);
            int j1 = __ldg(&g_rowstart[rp * N_ENT + tile_hi]);
            for (int j = j0 + eoff; j < j1; j += 16) {
                int2 rec = __ldg(&g_recs[j]);
                int drow = rec.x >> 7;
                int cl   = rec.x & 127;
                float v  = __int_as_float(rec.y);
                float4 q = *reinterpret_cast<const float4*>(&sY[cl * YW + d4 * 4]);
                float* dst = aout + (size_t)drow * D_EMB + d4 * 4;
                asm volatile("red.global.add.v4.f32 [%0], {%1,%2,%3,%4};"
                             :: "l"(dst), "f"(v * q.x), "f"(v * q.y),
                                "f"(v * q.z), "f"(v * q.w)
                             : "memory");
            }
        }

        float acc[8][4];
#pragma unroll
        for (int j = 0; j < 8; j++)
#pragma unroll
            for (int q = 0; q < 4; q++) acc[j][q] = 0.f;

#pragma unroll
        for (int ks = 0; ks < 4; ks++) {
            const int r0 = (wrow + g) * AW;
            const int r1 = (wrow + g + 8) * AW;
            const int eb = ks * 8 + t;
            uint32_t ah[4], al[4];
            ah[0] = sAh[r0 + eb];     ah[1] = sAh[r1 + eb];
            ah[2] = sAh[r0 + eb + 4]; ah[3] = sAh[r1 + eb + 4];
            al[0] = sAl[r0 + eb];     al[1] = sAl[r1 + eb];
            al[2] = sAl[r0 + eb + 4]; al[3] = sAl[r1 + eb + 4];

            const int kb0 = (ks * 8 + t) * BW;
            const int kb1 = (ks * 8 + t + 4) * BW;
#pragma unroll
            for (int j = 0; j < 8; j++) {
                int n = j * 8 + g;
                uint32_t bh0 = sBh[kb0 + n], bh1 = sBh[kb1 + n];
                uint32_t bl0 = sBl[kb0 + n], bl1 = sBl[kb1 + n];
                MMA_BF16(acc[j], ah, bh0, bh1);
                MMA_BF16(acc[j], ah, bl0, bl1);
                MMA_BF16(acc[j], al, bh0, bh1);
            }
        }

        __syncthreads();   // scatter_{r-1} reads done; MMA_r done reading B

        // ---- region2: write sY_r + stage B_{r+1} ----
#pragma unroll
        for (int j = 0; j < 8; j++) {
            int col = j * 8 + t * 2;
            *reinterpret_cast<float2*>(&sY[(wrow + g) * YW + col]) =
                make_float2(acc[j][0], acc[j][1]);
            *reinterpret_cast<float2*>(&sY[(wrow + g + 8) * YW + col]) =
                make_float2(acc[j][2], acc[j][3]);
        }
        if (r + 1 < R_REL) {
            const float* W = Wl + (size_t)(r + 1) * D_EMB * D_EMB;
#pragma unroll
            for (int i = 0; i < 8; i++) {
                int q  = tid + i * 256;
                int d  = q >> 5;
                int e2 = q & 31;
                float2 f = *reinterpret_cast<const float2*>(W + d * 64 + e2 * 2);
                uint32_t h, l; split_pair(f, h, l);
                sBh[e2 * BW + d] = h;
                sBl[e2 * BW + d] = l;
            }
        }
        __syncthreads();   // sY_r ready; B_{r+1} ready
    }

    // ---- final scatter (r = 15) ----
    {
        int rp = R_REL - 1;
        int j0 = __ldg(&g_rowstart[rp * N_ENT + base]);
        int j1 = __ldg(&g_rowstart[rp * N_ENT + tile_hi]);
        for (int j = j0 + eoff; j < j1; j += 16) {
            int2 rec = __ldg(&g_recs[j]);
            int drow = rec.x >> 7;
            int cl   = rec.x & 127;
            float v  = __int_as_float(rec.y);
            float4 q = *reinterpret_cast<const float4*>(&sY[cl * YW + d4 * 4]);
            float* dst = aout + (size_t)drow * D_EMB + d4 * 4;
            asm volatile("red.global.add.v4.f32 [%0], {%1,%2,%3,%4};"
                         :: "l"(dst), "f"(v * q.x), "f"(v * q.y),
                            "f"(v * q.z), "f"(v * q.w)
                         : "memory");
        }
    }
}

// ---------------------------------------------------------------------------
// L2 normalize rows of relu(g_acc2)
// ---------------------------------------------------------------------------
__global__ void k_normalize(float* __restrict__ out) {
    int row  = blockIdx.x * 8 + (threadIdx.x >> 5);
    int lane = threadIdx.x & 31;
    if (row >= N_ENT) return;
    const float* e = g_acc2 + (size_t)row * D_EMB;
    float v0 = fmaxf(e[lane], 0.f), v1 = fmaxf(e[lane + 32], 0.f);
    float ss = v0 * v0 + v1 * v1;
#pragma unroll
    for (int o = 16; o > 0; o >>= 1) ss += __shfl_xor_sync(0xFFFFFFFFu, ss, o);
    float s = 1.0f / fmaxf(sqrtf(ss), 1e-12f);
    out[(size_t)row * D_EMB + lane]      = v0 * s;
    out[(size_t)row * D_EMB + lane + 32] = v1 * s;
}

// ---------------------------------------------------------------------------
extern "C" void kernel_launch(void* const* d_in, const int* in_sizes, int n_in,
                              void* d_out, int out_size) {
    const float* x         = (const float*)d_in[0];
    const float* ent_emb   = (const float*)d_in[1];
    const float* rel_trans = (const float*)d_in[2];
    const int*   erow      = (const int*)d_in[3];
    const int*   ecol      = (const int*)d_in[4];
    const float* eval      = (const float*)d_in[5];
    float* out             = (float*)d_out;

    const int in_blocks   = (N_ENT + 63) / 64;                // 782
    const int tc_blocks   = (N_ENT + 127) / 128;              // 391
    const int edge_blocks = (NEDGE + 255) / 256;              // 6250
    const int elem_blocks = (N_ENT * D_EMB / 4 + 255) / 256;
    const int row_warps   = (N_ENT + 7) / 8;

    const size_t smem_in = 2 * 64 * KS_IN * sizeof(float);
    const size_t smem_f  = SM_TOT * sizeof(uint32_t);         // 89088
    cudaFuncSetAttribute(k_input_gemm,
                         cudaFuncAttributeMaxDynamicSharedMemorySize, (int)smem_in);
    cudaFuncSetAttribute(k_layer_fused,
                         cudaFuncAttributeMaxDynamicSharedMemorySize, (int)smem_f);

    k_input_gemm<<<in_blocks, 256, smem_in>>>(x, ent_emb, N_ENT);

    // CSC build (once; reused by both layers)
    k_zero_counts<<<(NK / 4 + 255) / 256, 256>>>();
    k_hist<<<edge_blocks, 256>>>(ecol);
    k_scan1<<<NCH, 256>>>();
    k_scan2<<<1, 1024>>>();
    k_scan3<<<(NK + 255) / 256, 256>>>();
    k_place<<<edge_blocks, 256>>>(erow, ecol, eval);

    // layer 1: A=emb -> scatter into acc1
    k_zero_acc<<<elem_blocks, 256>>>(0);
    k_layer_fused<<<tc_blocks, 256, smem_f>>>(rel_trans, 0, 0, N_ENT);
    // layer 2: A=relu(acc1) -> scatter into acc2
    k_zero_acc<<<elem_blocks, 256>>>(1);
    k_layer_fused<<<tc_blocks, 256, smem_f>>>(rel_trans, 1, 1, N_ENT);

    k_normalize<<<row_warps, 256>>>(out);
}

// round 12
// speedup vs baseline: 1.0792x; 1.0792x over previous
#include <cuda_runtime.h>
#include <cstdint>

#define N_ENT 50000
#define R_REL 16
#define D_EMB 64
#define F_IN  128
#define E_EDGE 100000
#define NEDGE (R_REL * E_EDGE)          // 1.6M
#define NK (R_REL * N_ENT)              // 800000 keys (r*N + col)
#define NL 2

// ---------------- scratch (device globals; allocation-free rule) ------------
__device__ float g_emb[(size_t)N_ENT * D_EMB];                 // 12.8 MB
__device__ float g_acc1[(size_t)N_ENT * D_EMB];                // 12.8 MB (L2-hot)
__device__ float g_acc2[(size_t)N_ENT * D_EMB];                // 12.8 MB (L2-hot)
__device__ int   g_counts[NK];
__device__ int   g_rowstart[NK + 1];
__device__ int   g_cursor[NK];
__device__ int2  g_recs[NEDGE];          // {(dest_row<<7)|col_local, val bits}

#define SCHUNK 1024
#define NCH ((NK + SCHUNK - 1) / SCHUNK)                       // 782
__device__ int   g_part[NCH];

#define CVT_BF16X2(res, a, b) \
    asm("cvt.rn.satfinite.bf16x2.f32 %0, %1, %2;" : "=r"(res) : "f"(b), "f"(a))

__device__ __forceinline__ void split_pair(float2 f, uint32_t& h, uint32_t& l) {
    CVT_BF16X2(h, f.x, f.y);
    float h0 = __uint_as_float(h << 16);
    float h1 = __uint_as_float(h & 0xFFFF0000u);
    CVT_BF16X2(l, f.x - h0, f.y - h1);
}

#define MMA_BF16(c, a, b0, b1) \
    asm volatile("mma.sync.aligned.m16n8k16.row.col.f32.bf16.bf16.f32 " \
        "{%0,%1,%2,%3}, {%4,%5,%6,%7}, {%8,%9}, {%0,%1,%2,%3};" \
        : "+f"((c)[0]), "+f"((c)[1]), "+f"((c)[2]), "+f"((c)[3]) \
        : "r"((a)[0]), "r"((a)[1]), "r"((a)[2]), "r"((a)[3]), \
          "r"(b0), "r"(b1))

#define AW 36
#define BW 68

// ---------------------------------------------------------------------------
// Input GEMM via HMMA: g_emb[n,d] = sum_k x[n,k] * ent_emb[k,d]  (K=128)
// Proven transform MMA mapping; K processed as two 64-halves with re-staging.
// B staging transposes ent_emb: sB*[kpair][d] packs (ent[2k][d], ent[2k+1][d]).
// ---------------------------------------------------------------------------
#define IN_SM_AH 0
#define IN_SM_AL (128 * AW)
#define IN_SM_BH (2 * 128 * AW)
#define IN_SM_BL (2 * 128 * AW + 32 * BW)
#define IN_SM_WORDS (2 * 128 * AW + 2 * 32 * BW)   // 13568 words

__global__ void __launch_bounds__(256)
k_input_hmma(const float* __restrict__ x,
             const float* __restrict__ ent_emb,
             int nrows) {
    extern __shared__ uint32_t sw[];
    uint32_t* sAh = sw + IN_SM_AH;
    uint32_t* sAl = sw + IN_SM_AL;
    uint32_t* sBh = sw + IN_SM_BH;
    uint32_t* sBl = sw + IN_SM_BL;

    const int tid  = threadIdx.x;
    const int base = blockIdx.x * 128;

    const int warp = tid >> 5;
    const int lane = tid & 31;
    const int g = lane >> 2;
    const int t = lane & 3;
    const int wrow = warp * 16;

    float acc[8][4];
#pragma unroll
    for (int j = 0; j < 8; j++)
#pragma unroll
        for (int q = 0; q < 4; q++) acc[j][q] = 0.f;

    for (int h = 0; h < 2; h++) {
        __syncthreads();   // prior half's MMA done before restage
        // stage A half: 128 rows x 32 epairs (k = h*64 + e2*2)
#pragma unroll
        for (int i = 0; i < 16; i++) {
            int p   = tid + i * 256;
            int row = p >> 5;
            int e2  = p & 31;
            float2 f = make_float2(0.f, 0.f);
            if (base + row < nrows)
                f = *reinterpret_cast<const float2*>(
                    x + (size_t)(base + row) * F_IN + h * 64 + e2 * 2);
            uint32_t hh, ll; split_pair(f, hh, ll);
            sAh[row * AW + e2] = hh;
            sAl[row * AW + e2] = ll;
        }
        // stage B half: kpair e2 (k = h*64+e2*2), d: pack (ent[k][d], ent[k+1][d])
#pragma unroll
        for (int i = 0; i < 8; i++) {
            int p  = tid + i * 256;
            int d  = p >> 5;
            int e2 = p & 31;
            int k  = h * 64 + e2 * 2;
            float2 f = make_float2(ent_emb[(size_t)k * D_EMB + d],
                                   ent_emb[(size_t)(k + 1) * D_EMB + d]);
            uint32_t hh, ll; split_pair(f, hh, ll);
            sBh[e2 * BW + d] = hh;
            sBl[e2 * BW + d] = ll;
        }
        __syncthreads();

#pragma unroll
        for (int ks = 0; ks < 4; ks++) {
            const int r0 = (wrow + g) * AW;
            const int r1 = (wrow + g + 8) * AW;
            const int eb = ks * 8 + t;
            uint32_t ah[4], al[4];
            ah[0] = sAh[r0 + eb];     ah[1] = sAh[r1 + eb];
            ah[2] = sAh[r0 + eb + 4]; ah[3] = sAh[r1 + eb + 4];
            al[0] = sAl[r0 + eb];     al[1] = sAl[r1 + eb];
            al[2] = sAl[r0 + eb + 4]; al[3] = sAl[r1 + eb + 4];

            const int kb0 = (ks * 8 + t) * BW;
            const int kb1 = (ks * 8 + t + 4) * BW;
#pragma unroll
            for (int j = 0; j < 8; j++) {
                int n = j * 8 + g;
                uint32_t bh0 = sBh[kb0 + n], bh1 = sBh[kb1 + n];
                uint32_t bl0 = sBl[kb0 + n], bl1 = sBl[kb1 + n];
                MMA_BF16(acc[j], ah, bh0, bh1);
                MMA_BF16(acc[j], ah, bl0, bl1);
                MMA_BF16(acc[j], al, bh0, bh1);
            }
        }
    }

    {
        int row0 = base + wrow + g;
        int row1 = row0 + 8;
#pragma unroll
        for (int j = 0; j < 8; j++) {
            int col = j * 8 + t * 2;
            if (row0 < nrows)
                *reinterpret_cast<float2*>(g_emb + (size_t)row0 * D_EMB + col) =
                    make_float2(acc[j][0], acc[j][1]);
            if (row1 < nrows)
                *reinterpret_cast<float2*>(g_emb + (size_t)row1 * D_EMB + col) =
                    make_float2(acc[j][2], acc[j][3]);
        }
    }
}

// ---------------------------------------------------------------------------
// CSC build over keys = r*N_ENT + col  (proven)
// ---------------------------------------------------------------------------
__global__ void k_zero_counts() {
    int i = blockIdx.x * blockDim.x + threadIdx.x;
    if (i < NK / 4)
        reinterpret_cast<int4*>(g_counts)[i] = make_int4(0, 0, 0, 0);
}

__global__ void k_hist(const int* __restrict__ ecol) {
    int i = blockIdx.x * blockDim.x + threadIdx.x;
    if (i >= NEDGE) return;
    int r = i / E_EDGE;
    atomicAdd(&g_counts[r * N_ENT + __ldg(ecol + i)], 1);
}

__global__ void k_scan1() {
    __shared__ int ss[256];
    int b = blockIdx.x, t = threadIdx.x;
    int base = b * SCHUNK + t * 4;
    int4 c = make_int4(0, 0, 0, 0);
    if (base < NK) c = *reinterpret_cast<const int4*>(&g_counts[base]);
    int s = c.x + c.y + c.z + c.w;
    ss[t] = s;
    __syncthreads();
    for (int off = 1; off < 256; off <<= 1) {
        int v = (t >= off) ? ss[t - off] : 0;
        __syncthreads();
        ss[t] += v;
        __syncthreads();
    }
    int excl = ss[t] - s;
    if (t == 255) g_part[b] = ss[t];
    if (base < NK) {
        int r = excl;
        g_rowstart[base + 0] = r; r += c.x;
        g_rowstart[base + 1] = r; r += c.y;
        g_rowstart[base + 2] = r; r += c.z;
        g_rowstart[base + 3] = r;
    }
}

__global__ void k_scan2() {
    __shared__ int sp[1024];
    int t = threadIdx.x;
    int v = (t < NCH) ? g_part[t] : 0;
    sp[t] = v;
    __syncthreads();
    for (int off = 1; off < 1024; off <<= 1) {
        int x = (t >= off) ? sp[t - off] : 0;
        __syncthreads();
        sp[t] += x;
        __syncthreads();
    }
    if (t < NCH) g_part[t] = sp[t] - v;
    if (t == 1023) g_rowstart[NK] = sp[1023];
}

__global__ void k_scan3() {
    int i = blockIdx.x * blockDim.x + threadIdx.x;
    if (i < NK) {
        int v = g_rowstart[i] + g_part[i >> 10];
        g_rowstart[i] = v;
        g_cursor[i] = v;
    }
}

// k_place also zeroes acc1 (grid-stride over float4s; acc1 first touched by
// layer-1 scatter which runs after this kernel).
__global__ void k_place(const int* __restrict__ erow,
                        const int* __restrict__ ecol,
                        const float* __restrict__ eval) {
    int i = blockIdx.x * blockDim.x + threadIdx.x;
    if (i < N_ENT * D_EMB / 4)
        reinterpret_cast<float4*>(g_acc1)[i] = make_float4(0.f, 0.f, 0.f, 0.f);
    if (i >= NEDGE) return;
    int r   = i / E_EDGE;
    int col = __ldg(ecol + i);
    int key = r * N_ENT + col;
    int pos = atomicAdd(&g_cursor[key], 1);
    g_recs[pos] = make_int2((__ldg(erow + i) << 7) | (col & 127),
                            __float_as_int(__ldg(eval + i)));
}

// ---------------------------------------------------------------------------
// FUSED layer — round-10 structure byte-for-byte (proven 430us), plus an
// epilogue that zeroes this CTA's acc2 slice when src_sel==0 (layer 1), so
// the standalone k_zero_acc launches disappear.
// ---------------------------------------------------------------------------
#define YW 68
#define SM_AH 0
#define SM_AL (128 * AW)                        // 4608
#define SM_B  (2 * 128 * AW)                    // 9216; buf stride 2*32*BW
#define BBUF  (2 * 32 * BW)                     // 4352 words per buffer (hi+lo)
#define SM_Y  (SM_B + 2 * BBUF)                 // 17920
#define SM_TOT (SM_Y + 128 * YW)                // 26624 words = 106496 B

__global__ void __launch_bounds__(256)
k_layer_fused(const float* __restrict__ rel_trans, int layer,
              int src_sel, int nrows) {
    extern __shared__ uint32_t sw[];
    uint32_t* sAh = sw + SM_AH;
    uint32_t* sAl = sw + SM_AL;
    float*    sY  = reinterpret_cast<float*>(sw + SM_Y);

    const int tid  = threadIdx.x;
    const int base = blockIdx.x * 128;
    const float* Wl   = rel_trans + (size_t)layer * R_REL * D_EMB * D_EMB;
    const float* Asrc = src_sel ? g_acc1 : g_emb;
    float*       aout = src_sel ? g_acc2 : g_acc1;

    // ---- stage A once ----
#pragma unroll
    for (int i = 0; i < 16; i++) {
        int p   = tid + i * 256;
        int row = p >> 5;
        int e2  = p & 31;
        float2 f = make_float2(0.f, 0.f);
        if (base + row < nrows)
            f = *reinterpret_cast<const float2*>(
                Asrc + (size_t)(base + row) * D_EMB + e2 * 2);
        if (src_sel) { f.x = fmaxf(f.x, 0.f); f.y = fmaxf(f.y, 0.f); }
        uint32_t h, l; split_pair(f, h, l);
        sAh[row * AW + e2] = h;
        sAl[row * AW + e2] = l;
    }

    // ---- stage B_0 into buffer 0 ----
    {
        uint32_t* bh = sw + SM_B;
        uint32_t* bl = bh + 32 * BW;
#pragma unroll
        for (int i = 0; i < 8; i++) {
            int p  = tid + i * 256;
            int d  = p >> 5;
            int e2 = p & 31;
            float2 f = *reinterpret_cast<const float2*>(Wl + d * 64 + e2 * 2);
            uint32_t h, l; split_pair(f, h, l);
            bh[e2 * BW + d] = h;
            bl[e2 * BW + d] = l;
        }
    }
    __syncthreads();

    const int warp = tid >> 5;
    const int lane = tid & 31;
    const int g = lane >> 2;
    const int t = lane & 3;
    const int wrow = warp * 16;
    const int d4 = tid & 15;
    const int eoff = tid >> 4;
    const int tile_hi = (base + 128 < nrows) ? base + 128 : nrows;

    int p = 0;
    for (int r = 0; r < R_REL; r++) {
        const uint32_t* bh = sw + SM_B + p * BBUF;
        const uint32_t* bl = bh + 32 * BW;

        // ---- MMA (registers only) ----
        float acc[8][4];
#pragma unroll
        for (int j = 0; j < 8; j++)
#pragma unroll
            for (int q = 0; q < 4; q++) acc[j][q] = 0.f;

#pragma unroll
        for (int ks = 0; ks < 4; ks++) {
            const int r0 = (wrow + g) * AW;
            const int r1 = (wrow + g + 8) * AW;
            const int eb = ks * 8 + t;
            uint32_t ah[4], al[4];
            ah[0] = sAh[r0 + eb];     ah[1] = sAh[r1 + eb];
            ah[2] = sAh[r0 + eb + 4]; ah[3] = sAh[r1 + eb + 4];
            al[0] = sAl[r0 + eb];     al[1] = sAl[r1 + eb];
            al[2] = sAl[r0 + eb + 4]; al[3] = sAl[r1 + eb + 4];

            const int kb0 = (ks * 8 + t) * BW;
            const int kb1 = (ks * 8 + t + 4) * BW;
#pragma unroll
            for (int j = 0; j < 8; j++) {
                int n = j * 8 + g;
                uint32_t bh0 = bh[kb0 + n], bh1 = bh[kb1 + n];
                uint32_t bl0 = bl[kb0 + n], bl1 = bl[kb1 + n];
                MMA_BF16(acc[j], ah, bh0, bh1);
                MMA_BF16(acc[j], ah, bl0, bl1);
                MMA_BF16(acc[j], al, bh0, bh1);
            }
        }

        // ---- stage next B into other buffer ----
        if (r + 1 < R_REL) {
            const float* W = Wl + (size_t)(r + 1) * D_EMB * D_EMB;
            uint32_t* nbh = sw + SM_B + (p ^ 1) * BBUF;
            uint32_t* nbl = nbh + 32 * BW;
#pragma unroll
            for (int i = 0; i < 8; i++) {
                int q  = tid + i * 256;
                int d  = q >> 5;
                int e2 = q & 31;
                float2 f = *reinterpret_cast<const float2*>(W + d * 64 + e2 * 2);
                uint32_t h, l; split_pair(f, h, l);
                nbh[e2 * BW + d] = h;
                nbl[e2 * BW + d] = l;
            }
        }

        __syncthreads();   // scatter_{r-1} done reading sY; safe to overwrite

        // ---- write Y tile to SMEM ----
#pragma unroll
        for (int j = 0; j < 8; j++) {
            int col = j * 8 + t * 2;
            *reinterpret_cast<float2*>(&sY[(wrow + g) * YW + col]) =
                make_float2(acc[j][0], acc[j][1]);
            *reinterpret_cast<float2*>(&sY[(wrow + g + 8) * YW + col]) =
                make_float2(acc[j][2], acc[j][3]);
        }

        __syncthreads();   // sY ready

        // ---- scatter this (tile, r)'s edges from SMEM ----
        {
            int j0 = __ldg(&g_rowstart[r * N_ENT + base]);
            int j1 = __ldg(&g_rowstart[r * N_ENT + tile_hi]);
            for (int j = j0 + eoff; j < j1; j += 16) {
                int2 rec = __ldg(&g_recs[j]);
                int drow = rec.x >> 7;
                int cl   = rec.x & 127;
                float v  = __int_as_float(rec.y);
                float4 q = *reinterpret_cast<const float4*>(&sY[cl * YW + d4 * 4]);
                float* dst = aout + (size_t)drow * D_EMB + d4 * 4;
                asm volatile("red.global.add.v4.f32 [%0], {%1,%2,%3,%4};"
                             :: "l"(dst), "f"(v * q.x), "f"(v * q.y),
                                "f"(v * q.z), "f"(v * q.w)
                             : "memory");
            }
        }

        p ^= 1;
    }

    // ---- layer-1 epilogue: zero this CTA's acc2 slice (acc2 untouched by
    // layer 1 otherwise; replaces standalone k_zero_acc) ----
    if (src_sel == 0) {
#pragma unroll
        for (int i = 0; i < 8; i++) {
            int q = tid + i * 256;
            int row = base + (q >> 4);
            if (row < nrows)
                reinterpret_cast<float4*>(g_acc2)[(size_t)row * 16 + (q & 15)] =
                    make_float4(0.f, 0.f, 0.f, 0.f);
        }
    }
}

// ---------------------------------------------------------------------------
// L2 normalize rows of relu(g_acc2)
// ---------------------------------------------------------------------------
__global__ void k_normalize(float* __restrict__ out) {
    int row  = blockIdx.x * 8 + (threadIdx.x >> 5);
    int lane = threadIdx.x & 31;
    if (row >= N_ENT) return;
    const float* e = g_acc2 + (size_t)row * D_EMB;
    float v0 = fmaxf(e[lane], 0.f), v1 = fmaxf(e[lane + 32], 0.f);
    float ss = v0 * v0 + v1 * v1;
#pragma unroll
    for (int o = 16; o > 0; o >>= 1) ss += __shfl_xor_sync(0xFFFFFFFFu, ss, o);
    float s = 1.0f / fmaxf(sqrtf(ss), 1e-12f);
    out[(size_t)row * D_EMB + lane]      = v0 * s;
    out[(size_t)row * D_EMB + lane + 32] = v1 * s;
}

// ---------------------------------------------------------------------------
extern "C" void kernel_launch(void* const* d_in, const int* in_sizes, int n_in,
                              void* d_out, int out_size) {
    const float* x         = (const float*)d_in[0];
    const float* ent_emb   = (const float*)d_in[1];
    const float* rel_trans = (const float*)d_in[2];
    const int*   erow      = (const int*)d_in[3];
    const int*   ecol      = (const int*)d_in[4];
    const float* eval      = (const float*)d_in[5];
    float* out             = (float*)d_out;

    const int tc_blocks   = (N_ENT + 127) / 128;              // 391
    const int edge_blocks = (NEDGE + 255) / 256;              // 6250
    const int row_warps   = (N_ENT + 7) / 8;

    const size_t smem_in = IN_SM_WORDS * sizeof(uint32_t);    // 54272
    const size_t smem_f  = SM_TOT * sizeof(uint32_t);         // 106496
    cudaFuncSetAttribute(k_input_hmma,
                         cudaFuncAttributeMaxDynamicSharedMemorySize, (int)smem_in);
    cudaFuncSetAttribute(k_layer_fused,
                         cudaFuncAttributeMaxDynamicSharedMemorySize, (int)smem_f);

    k_input_hmma<<<tc_blocks, 256, smem_in>>>(x, ent_emb, N_ENT);

    // CSC build (once; reused by both layers). k_place also zeroes acc1.
    k_zero_counts<<<(NK / 4 + 255) / 256, 256>>>();
    k_hist<<<edge_blocks, 256>>>(ecol);
    k_scan1<<<NCH, 256>>>();
    k_scan2<<<1, 1024>>>();
    k_scan3<<<(NK + 255) / 256, 256>>>();
    k_place<<<edge_blocks, 256>>>(erow, ecol, eval);

    // layer 1: A=emb -> scatter into acc1 (epilogue zeroes acc2)
    k_layer_fused<<<tc_blocks, 256, smem_f>>>(rel_trans, 0, 0, N_ENT);
    // layer 2: A=relu(acc1) -> scatter into acc2
    k_layer_fused<<<tc_blocks, 256, smem_f>>>(rel_trans, 1, 1, N_ENT);

    k_normalize<<<row_warps, 256>>>(out);
}

// round 13
// speedup vs baseline: 1.1272x; 1.0445x over previous
#include <cuda_runtime.h>
#include <cstdint>

#define N_ENT 50000
#define R_REL 16
#define D_EMB 64
#define F_IN  128
#define E_EDGE 100000
#define NEDGE (R_REL * E_EDGE)          // 1.6M
#define NK (R_REL * N_ENT)              // 800000 keys (r*N + col)
#define NL 2

// ---------------- scratch (device globals; allocation-free rule) ------------
__device__ float g_emb[(size_t)N_ENT * D_EMB];                 // 12.8 MB
__device__ float g_acc1[(size_t)N_ENT * D_EMB];                // 12.8 MB (L2-hot)
__device__ float g_acc2[(size_t)N_ENT * D_EMB];                // 12.8 MB (L2-hot)
__device__ int   g_counts[NK];
__device__ int   g_rowstart[NK + 1];
__device__ int   g_cursor[NK];
__device__ int2  g_recs[NEDGE];          // {(dest_row<<7)|col_local, val bits}
__device__ int   g_done;                 // scan12 last-block ticket

#define SCHUNK 1024
#define NCH ((NK + SCHUNK - 1) / SCHUNK)                       // 782
__device__ int   g_part[NCH];

#define CVT_BF16X2(res, a, b) \
    asm("cvt.rn.satfinite.bf16x2.f32 %0, %1, %2;" : "=r"(res) : "f"(b), "f"(a))

__device__ __forceinline__ void split_pair(float2 f, uint32_t& h, uint32_t& l) {
    CVT_BF16X2(h, f.x, f.y);
    float h0 = __uint_as_float(h << 16);
    float h1 = __uint_as_float(h & 0xFFFF0000u);
    CVT_BF16X2(l, f.x - h0, f.y - h1);
}

#define MMA_BF16(c, a, b0, b1) \
    asm volatile("mma.sync.aligned.m16n8k16.row.col.f32.bf16.bf16.f32 " \
        "{%0,%1,%2,%3}, {%4,%5,%6,%7}, {%8,%9}, {%0,%1,%2,%3};" \
        : "+f"((c)[0]), "+f"((c)[1]), "+f"((c)[2]), "+f"((c)[3]) \
        : "r"((a)[0]), "r"((a)[1]), "r"((a)[2]), "r"((a)[3]), \
          "r"(b0), "r"(b1))

#define AW 36
#define BW 68

// ---------------------------------------------------------------------------
// Input GEMM via HMMA (round-12 proven) + epilogue zeroes g_counts & g_done
// ---------------------------------------------------------------------------
#define IN_SM_AH 0
#define IN_SM_AL (128 * AW)
#define IN_SM_BH (2 * 128 * AW)
#define IN_SM_BL (2 * 128 * AW + 32 * BW)
#define IN_SM_WORDS (2 * 128 * AW + 2 * 32 * BW)   // 13568 words

__global__ void __launch_bounds__(256)
k_input_hmma(const float* __restrict__ x,
             const float* __restrict__ ent_emb,
             int nrows) {
    extern __shared__ uint32_t sw[];
    uint32_t* sAh = sw + IN_SM_AH;
    uint32_t* sAl = sw + IN_SM_AL;
    uint32_t* sBh = sw + IN_SM_BH;
    uint32_t* sBl = sw + IN_SM_BL;

    const int tid  = threadIdx.x;
    const int base = blockIdx.x * 128;

    const int warp = tid >> 5;
    const int lane = tid & 31;
    const int g = lane >> 2;
    const int t = lane & 3;
    const int wrow = warp * 16;

    float acc[8][4];
#pragma unroll
    for (int j = 0; j < 8; j++)
#pragma unroll
        for (int q = 0; q < 4; q++) acc[j][q] = 0.f;

    for (int h = 0; h < 2; h++) {
        __syncthreads();
#pragma unroll
        for (int i = 0; i < 16; i++) {
            int p   = tid + i * 256;
            int row = p >> 5;
            int e2  = p & 31;
            float2 f = make_float2(0.f, 0.f);
            if (base + row < nrows)
                f = *reinterpret_cast<const float2*>(
                    x + (size_t)(base + row) * F_IN + h * 64 + e2 * 2);
            uint32_t hh, ll; split_pair(f, hh, ll);
            sAh[row * AW + e2] = hh;
            sAl[row * AW + e2] = ll;
        }
#pragma unroll
        for (int i = 0; i < 8; i++) {
            int p  = tid + i * 256;
            int d  = p >> 5;
            int e2 = p & 31;
            int k  = h * 64 + e2 * 2;
            float2 f = make_float2(ent_emb[(size_t)k * D_EMB + d],
                                   ent_emb[(size_t)(k + 1) * D_EMB + d]);
            uint32_t hh, ll; split_pair(f, hh, ll);
            sBh[e2 * BW + d] = hh;
            sBl[e2 * BW + d] = ll;
        }
        __syncthreads();

#pragma unroll
        for (int ks = 0; ks < 4; ks++) {
            const int r0 = (wrow + g) * AW;
            const int r1 = (wrow + g + 8) * AW;
            const int eb = ks * 8 + t;
            uint32_t ah[4], al[4];
            ah[0] = sAh[r0 + eb];     ah[1] = sAh[r1 + eb];
            ah[2] = sAh[r0 + eb + 4]; ah[3] = sAh[r1 + eb + 4];
            al[0] = sAl[r0 + eb];     al[1] = sAl[r1 + eb];
            al[2] = sAl[r0 + eb + 4]; al[3] = sAl[r1 + eb + 4];

            const int kb0 = (ks * 8 + t) * BW;
            const int kb1 = (ks * 8 + t + 4) * BW;
#pragma unroll
            for (int j = 0; j < 8; j++) {
                int n = j * 8 + g;
                uint32_t bh0 = sBh[kb0 + n], bh1 = sBh[kb1 + n];
                uint32_t bl0 = sBl[kb0 + n], bl1 = sBl[kb1 + n];
                MMA_BF16(acc[j], ah, bh0, bh1);
                MMA_BF16(acc[j], ah, bl0, bl1);
                MMA_BF16(acc[j], al, bh0, bh1);
            }
        }
    }

    {
        int row0 = base + wrow + g;
        int row1 = row0 + 8;
#pragma unroll
        for (int j = 0; j < 8; j++) {
            int col = j * 8 + t * 2;
            if (row0 < nrows)
                *reinterpret_cast<float2*>(g_emb + (size_t)row0 * D_EMB + col) =
                    make_float2(acc[j][0], acc[j][1]);
            if (row1 < nrows)
                *reinterpret_cast<float2*>(g_emb + (size_t)row1 * D_EMB + col) =
                    make_float2(acc[j][2], acc[j][3]);
        }
    }

    // epilogue: zero counts + scan ticket (used by later CSC kernels)
    {
        int gt = blockIdx.x * 256 + tid;
        int stride = gridDim.x * 256;
        for (int i = gt; i < NK / 4; i += stride)
            reinterpret_cast<int4*>(g_counts)[i] = make_int4(0, 0, 0, 0);
        if (gt == 0) g_done = 0;
    }
}

// ---------------------------------------------------------------------------
// CSC build over keys = r*N_ENT + col  (proven; scan1+scan2 merged)
// ---------------------------------------------------------------------------
__global__ void k_hist(const int* __restrict__ ecol) {
    int i = blockIdx.x * blockDim.x + threadIdx.x;
    if (i >= NEDGE) return;
    int r = i / E_EDGE;
    atomicAdd(&g_counts[r * N_ENT + __ldg(ecol + i)], 1);
}

__global__ void k_scan12() {
    __shared__ int ss[256];
    __shared__ int sdone;
    int b = blockIdx.x, t = threadIdx.x;
    int base = b * SCHUNK + t * 4;
    int4 c = make_int4(0, 0, 0, 0);
    if (base < NK) c = *reinterpret_cast<const int4*>(&g_counts[base]);
    int s = c.x + c.y + c.z + c.w;
    ss[t] = s;
    __syncthreads();
    for (int off = 1; off < 256; off <<= 1) {
        int v = (t >= off) ? ss[t - off] : 0;
        __syncthreads();
        ss[t] += v;
        __syncthreads();
    }
    int excl = ss[t] - s;
    if (t == 255) g_part[b] = ss[t];
    if (base < NK) {
        int r = excl;
        g_rowstart[base + 0] = r; r += c.x;
        g_rowstart[base + 1] = r; r += c.y;
        g_rowstart[base + 2] = r; r += c.z;
        g_rowstart[base + 3] = r;
    }

    // last block performs the chunk-offset scan (threadFenceReduction pattern)
    if (t == 255) {
        __threadfence();
        int old = atomicAdd(&g_done, 1);
        sdone = (old == gridDim.x - 1) ? 1 : 0;
    }
    __syncthreads();
    if (sdone) {
        int v0 = 0, v1 = 0, v2 = 0, v3 = 0;
        int i0 = t * 4;
        if (i0 + 0 < NCH) v0 = g_part[i0 + 0];
        if (i0 + 1 < NCH) v1 = g_part[i0 + 1];
        if (i0 + 2 < NCH) v2 = g_part[i0 + 2];
        if (i0 + 3 < NCH) v3 = g_part[i0 + 3];
        int l0 = v0, l1 = l0 + v1, l2 = l1 + v2, l3 = l2 + v3;
        __syncthreads();           // ss reuse
        ss[t] = l3;
        __syncthreads();
        for (int off = 1; off < 256; off <<= 1) {
            int v = (t >= off) ? ss[t - off] : 0;
            __syncthreads();
            ss[t] += v;
            __syncthreads();
        }
        int exclT = ss[t] - l3;
        if (i0 + 0 < NCH) g_part[i0 + 0] = exclT;
        if (i0 + 1 < NCH) g_part[i0 + 1] = exclT + l0;
        if (i0 + 2 < NCH) g_part[i0 + 2] = exclT + l1;
        if (i0 + 3 < NCH) g_part[i0 + 3] = exclT + l2;
        if (t == 255) g_rowstart[NK] = ss[255];
    }
}

__global__ void k_scan3() {
    int i = blockIdx.x * blockDim.x + threadIdx.x;
    if (i < NK) {
        int v = g_rowstart[i] + g_part[i >> 10];
        g_rowstart[i] = v;
        g_cursor[i] = v;
    }
}

// k_place also zeroes acc1 (proven)
__global__ void k_place(const int* __restrict__ erow,
                        const int* __restrict__ ecol,
                        const float* __restrict__ eval) {
    int i = blockIdx.x * blockDim.x + threadIdx.x;
    if (i < N_ENT * D_EMB / 4)
        reinterpret_cast<float4*>(g_acc1)[i] = make_float4(0.f, 0.f, 0.f, 0.f);
    if (i >= NEDGE) return;
    int r   = i / E_EDGE;
    int col = __ldg(ecol + i);
    int key = r * N_ENT + col;
    int pos = atomicAdd(&g_cursor[key], 1);
    g_recs[pos] = make_int2((__ldg(erow + i) << 7) | (col & 127),
                            __float_as_int(__ldg(eval + i)));
}

// ---------------------------------------------------------------------------
// FUSED layer — round-10/12 proven structure, with:
//  * A fragments preloaded to registers (A identical across relations)
//  * sY aliases the A smem region (A consumed into regs before first sY write;
//    separated by the first in-loop __syncthreads) -> smem 71.7KB, 2 CTAs/SM
// ---------------------------------------------------------------------------
#define YW 68
#define SM_A 0                                  // A hi/lo: 2*128*AW = 9216 w
#define SM_B  (2 * 128 * AW)                    // 9216
#define BBUF  (2 * 32 * BW)                     // 4352 words per buffer
#define SM_TOT (SM_B + 2 * BBUF)                // 17920 words = 71680 B
// sY aliases words [0, 128*YW) = 8704 <= 9216

__global__ void __launch_bounds__(256, 2)
k_layer_fused(const float* __restrict__ rel_trans, int layer,
              int src_sel, int nrows) {
    extern __shared__ uint32_t sw[];
    uint32_t* sAh = sw + SM_A;
    uint32_t* sAl = sw + SM_A + 128 * AW;
    float*    sY  = reinterpret_cast<float*>(sw);   // aliases A region

    const int tid  = threadIdx.x;
    const int base = blockIdx.x * 128;
    const float* Wl   = rel_trans + (size_t)layer * R_REL * D_EMB * D_EMB;
    const float* Asrc = src_sel ? g_acc1 : g_emb;
    float*       aout = src_sel ? g_acc2 : g_acc1;

    // ---- stage A once ----
#pragma unroll
    for (int i = 0; i < 16; i++) {
        int p   = tid + i * 256;
        int row = p >> 5;
        int e2  = p & 31;
        float2 f = make_float2(0.f, 0.f);
        if (base + row < nrows)
            f = *reinterpret_cast<const float2*>(
                Asrc + (size_t)(base + row) * D_EMB + e2 * 2);
        if (src_sel) { f.x = fmaxf(f.x, 0.f); f.y = fmaxf(f.y, 0.f); }
        uint32_t h, l; split_pair(f, h, l);
        sAh[row * AW + e2] = h;
        sAl[row * AW + e2] = l;
    }

    // ---- stage B_0 into buffer 0 ----
    {
        uint32_t* bh = sw + SM_B;
        uint32_t* bl = bh + 32 * BW;
#pragma unroll
        for (int i = 0; i < 8; i++) {
            int p  = tid + i * 256;
            int d  = p >> 5;
            int e2 = p & 31;
            float2 f = *reinterpret_cast<const float2*>(Wl + d * 64 + e2 * 2);
            uint32_t h, l; split_pair(f, h, l);
            bh[e2 * BW + d] = h;
            bl[e2 * BW + d] = l;
        }
    }
    __syncthreads();

    const int warp = tid >> 5;
    const int lane = tid & 31;
    const int g = lane >> 2;
    const int t = lane & 3;
    const int wrow = warp * 16;
    const int d4 = tid & 15;
    const int eoff = tid >> 4;
    const int tile_hi = (base + 128 < nrows) ? base + 128 : nrows;

    // ---- preload A fragments into registers (reused for all 16 relations) ----
    uint32_t fah[4][4], fal[4][4];
#pragma unroll
    for (int ks = 0; ks < 4; ks++) {
        const int r0 = (wrow + g) * AW;
        const int r1 = (wrow + g + 8) * AW;
        const int eb = ks * 8 + t;
        fah[ks][0] = sAh[r0 + eb];     fah[ks][1] = sAh[r1 + eb];
        fah[ks][2] = sAh[r0 + eb + 4]; fah[ks][3] = sAh[r1 + eb + 4];
        fal[ks][0] = sAl[r0 + eb];     fal[ks][1] = sAl[r1 + eb];
        fal[ks][2] = sAl[r0 + eb + 4]; fal[ks][3] = sAl[r1 + eb + 4];
    }

    int p = 0;
    for (int r = 0; r < R_REL; r++) {
        const uint32_t* bh = sw + SM_B + p * BBUF;
        const uint32_t* bl = bh + 32 * BW;

        // ---- MMA (A from registers) ----
        float acc[8][4];
#pragma unroll
        for (int j = 0; j < 8; j++)
#pragma unroll
            for (int q = 0; q < 4; q++) acc[j][q] = 0.f;

#pragma unroll
        for (int ks = 0; ks < 4; ks++) {
            const int kb0 = (ks * 8 + t) * BW;
            const int kb1 = (ks * 8 + t + 4) * BW;
#pragma unroll
            for (int j = 0; j < 8; j++) {
                int n = j * 8 + g;
                uint32_t bh0 = bh[kb0 + n], bh1 = bh[kb1 + n];
                uint32_t bl0 = bl[kb0 + n], bl1 = bl[kb1 + n];
                MMA_BF16(acc[j], fah[ks], bh0, bh1);
                MMA_BF16(acc[j], fah[ks], bl0, bl1);
                MMA_BF16(acc[j], fal[ks], bh0, bh1);
            }
        }

        // ---- stage next B into other buffer ----
        if (r + 1 < R_REL) {
            const float* W = Wl + (size_t)(r + 1) * D_EMB * D_EMB;
            uint32_t* nbh = sw + SM_B + (p ^ 1) * BBUF;
            uint32_t* nbl = nbh + 32 * BW;
#pragma unroll
            for (int i = 0; i < 8; i++) {
                int q  = tid + i * 256;
                int d  = q >> 5;
                int e2 = q & 31;
                float2 f = *reinterpret_cast<const float2*>(W + d * 64 + e2 * 2);
                uint32_t h, l; split_pair(f, h, l);
                nbh[e2 * BW + d] = h;
                nbl[e2 * BW + d] = l;
            }
        }

        __syncthreads();   // scatter_{r-1} done with sY; frags loaded (r=0)

        // ---- write Y tile to SMEM (aliases A region) ----
#pragma unroll
        for (int j = 0; j < 8; j++) {
            int col = j * 8 + t * 2;
            *reinterpret_cast<float2*>(&sY[(wrow + g) * YW + col]) =
                make_float2(acc[j][0], acc[j][1]);
            *reinterpret_cast<float2*>(&sY[(wrow + g + 8) * YW + col]) =
                make_float2(acc[j][2], acc[j][3]);
        }

        __syncthreads();   // sY ready

        // ---- scatter this (tile, r)'s edges from SMEM ----
        {
            int j0 = __ldg(&g_rowstart[r * N_ENT + base]);
            int j1 = __ldg(&g_rowstart[r * N_ENT + tile_hi]);
            for (int j = j0 + eoff; j < j1; j += 16) {
                int2 rec = __ldg(&g_recs[j]);
                int drow = rec.x >> 7;
                int cl   = rec.x & 127;
                float v  = __int_as_float(rec.y);
                float4 q = *reinterpret_cast<const float4*>(&sY[cl * YW + d4 * 4]);
                float* dst = aout + (size_t)drow * D_EMB + d4 * 4;
                asm volatile("red.global.add.v4.f32 [%0], {%1,%2,%3,%4};"
                             :: "l"(dst), "f"(v * q.x), "f"(v * q.y),
                                "f"(v * q.z), "f"(v * q.w)
                             : "memory");
            }
        }

        p ^= 1;
    }

    // ---- layer-1 epilogue: zero this CTA's acc2 slice (proven) ----
    if (src_sel == 0) {
#pragma unroll
        for (int i = 0; i < 8; i++) {
            int q = tid + i * 256;
            int row = base + (q >> 4);
            if (row < nrows)
                reinterpret_cast<float4*>(g_acc2)[(size_t)row * 16 + (q & 15)] =
                    make_float4(0.f, 0.f, 0.f, 0.f);
        }
    }
}

// ---------------------------------------------------------------------------
// L2 normalize rows of relu(g_acc2)
// ---------------------------------------------------------------------------
__global__ void k_normalize(float* __restrict__ out) {
    int row  = blockIdx.x * 8 + (threadIdx.x >> 5);
    int lane = threadIdx.x & 31;
    if (row >= N_ENT) return;
    const float* e = g_acc2 + (size_t)row * D_EMB;
    float v0 = fmaxf(e[lane], 0.f), v1 = fmaxf(e[lane + 32], 0.f);
    float ss = v0 * v0 + v1 * v1;
#pragma unroll
    for (int o = 16; o > 0; o >>= 1) ss += __shfl_xor_sync(0xFFFFFFFFu, ss, o);
    float s = 1.0f / fmaxf(sqrtf(ss), 1e-12f);
    out[(size_t)row * D_EMB + lane]      = v0 * s;
    out[(size_t)row * D_EMB + lane + 32] = v1 * s;
}

// ---------------------------------------------------------------------------
extern "C" void kernel_launch(void* const* d_in, const int* in_sizes, int n_in,
                              void* d_out, int out_size) {
    const float* x         = (const float*)d_in[0];
    const float* ent_emb   = (const float*)d_in[1];
    const float* rel_trans = (const float*)d_in[2];
    const int*   erow      = (const int*)d_in[3];
    const int*   ecol      = (const int*)d_in[4];
    const float* eval      = (const float*)d_in[5];
    float* out             = (float*)d_out;

    const int tc_blocks   = (N_ENT + 127) / 128;              // 391
    const int edge_blocks = (NEDGE + 255) / 256;              // 6250
    const int row_warps   = (N_ENT + 7) / 8;

    const size_t smem_in = IN_SM_WORDS * sizeof(uint32_t);    // 54272
    const size_t smem_f  = SM_TOT * sizeof(uint32_t);         // 71680
    cudaFuncSetAttribute(k_input_hmma,
                         cudaFuncAttributeMaxDynamicSharedMemorySize, (int)smem_in);
    cudaFuncSetAttribute(k_layer_fused,
                         cudaFuncAttributeMaxDynamicSharedMemorySize, (int)smem_f);

    // launch order puts k_layer_fused(l=0) at ncu capture idx 5 (-s 5 -c 1)
    k_input_hmma<<<tc_blocks, 256, smem_in>>>(x, ent_emb, N_ENT);    // 0 (+zero)
    k_hist<<<edge_blocks, 256>>>(ecol);                              // 1
    k_scan12<<<NCH, 256>>>();                                        // 2
    k_scan3<<<(NK + 255) / 256, 256>>>();                            // 3
    k_place<<<edge_blocks, 256>>>(erow, ecol, eval);                 // 4 (+zero acc1)
    k_layer_fused<<<tc_blocks, 256, smem_f>>>(rel_trans, 0, 0, N_ENT); // 5
    k_layer_fused<<<tc_blocks, 256, smem_f>>>(rel_trans, 1, 1, N_ENT); // 6
    k_normalize<<<row_warps, 256>>>(out);                            // 7
}